// round 11
// baseline (speedup 1.0000x reference)
#include <cuda_runtime.h>

// LSTM_40948218200110: B=4096, T=1024, I=8, H=4 (PyTorch gate order) + FC[H->1].
// R9 = R7 + two chains per thread. 16 lanes per element-group (lane u = r*4+k),
// each group advances TWO batch elements; warp-wide shuffles serve both chains'
// exchange at one wavefront each logical shuffle, weights shared between chains.
// 1024 warps, grid=128 x 256 threads -> at most ONE block per SM (uniform load).
// Packed fma.rn.f32x2 dot products; x staged via smem (coalesced LDG -> LDS.128).

#define T_STEPS 1024
#define I_DIM   8
#define EPB     32            // elements per block (16 groups x 2 chains)
#define BLOCK   256           // threads per block
#define CH_STEPS 8            // timesteps per smem chunk
#define NCHUNK  (T_STEPS / CH_STEPS)   // 128
#define STRIDE4 17            // float4 stride per element in smem (pad 16->17)

typedef unsigned long long ull;

__device__ __forceinline__ float tanh_fast(float x) {
    float y;
    asm("tanh.approx.f32 %0, %1;" : "=f"(y) : "f"(x));
    return y;
}
__device__ __forceinline__ ull ffma2(ull a, ull b, ull c) {
    ull d;
    asm("fma.rn.f32x2 %0, %1, %2, %3;" : "=l"(d) : "l"(a), "l"(b), "l"(c));
    return d;
}
__device__ __forceinline__ ull pack2(float lo, float hi) {
    ull d;
    asm("mov.b64 %0, {%1, %2};" : "=l"(d) : "f"(lo), "f"(hi));
    return d;
}
__device__ __forceinline__ float hsum2(ull v) {
    float lo, hi;
    asm("mov.b64 {%0, %1}, %2;" : "=f"(lo), "=f"(hi) : "l"(v));
    return lo + hi;
}

struct Chain { float h0, h1, h2, h3, c, hs; };

__global__ __launch_bounds__(BLOCK, 1) void lstm_kernel(
    const float* __restrict__ x,     // [B, T, I]
    const float* __restrict__ Wih,   // [16, 8]
    const float* __restrict__ Whh,   // [16, 4]
    const float* __restrict__ bih,   // [16]
    const float* __restrict__ bhh,   // [16]
    const float* __restrict__ fcw,   // [1, 4]
    const float* __restrict__ fcb,   // [1]
    float* __restrict__ out,         // [B, 1]
    int B)
{
    __shared__ float4 sm[2][EPB * STRIDE4];

    const int t = threadIdx.x;
    const int g = t >> 4;             // group 0..15
    const int u = t & 15;             // lane within group
    const int k = u & 3;              // hidden unit
    const int r = u >> 2;             // gate: 0=i,1=f,2=g,3=o
    const int eA = 2 * g;
    const int eB = 2 * g + 1;
    const int bA = blockIdx.x * EPB + eA;
    const int bB = blockIdx.x * EPB + eB;

    const int row = r * 4 + k;
    // sigmoid(z)=0.5*tanh(0.5z)+0.5 -> fold 0.5 into weights for i/f/o rows.
    const float s    = (r == 2) ? 1.0f : 0.5f;
    const float actM = (r == 2) ? 1.0f : 0.5f;
    const float actB = (r == 2) ? 0.0f : 0.5f;

    // Weights SHARED by both chains (same row).
    ull wx[4], wh[2], bia;
#pragma unroll
    for (int j = 0; j < 4; j++)
        wx[j] = pack2(s * Wih[row * I_DIM + 2 * j], s * Wih[row * I_DIM + 2 * j + 1]);
    wh[0] = pack2(s * Whh[row * 4 + 0], s * Whh[row * 4 + 1]);
    wh[1] = pack2(s * Whh[row * 4 + 2], s * Whh[row * 4 + 3]);
    bia = pack2(s * (bih[row] + bhh[row]), 0.0f);

    Chain cA = {0.f, 0.f, 0.f, 0.f, 0.f, 0.f};
    Chain cB = {0.f, 0.f, 0.f, 0.f, 0.f, 0.f};
    const unsigned FULL = 0xffffffffu;

    auto STEP = [&](Chain& ch, ulonglong2 xlo, ulonglong2 xhi) {
        const ull h01 = pack2(ch.h0, ch.h1);
        const ull h23 = pack2(ch.h2, ch.h3);

        ull acc = ffma2(wx[0], xlo.x, bia);
        acc = ffma2(wx[1], xlo.y, acc);
        acc = ffma2(wx[2], xhi.x, acc);
        acc = ffma2(wx[3], xhi.y, acc);
        acc = ffma2(wh[0], h01, acc);            // recurrent (critical path)
        acc = ffma2(wh[1], h23, acc);
        const float z = hsum2(acc);

        const float a = fmaf(tanh_fast(z), actM, actB);   // gate activation

        // gather f, g, o activations of unit k (parallel width-16 shuffles)
        const float fv = __shfl_sync(FULL, a, k + 4,  16);
        const float gv = __shfl_sync(FULL, a, k + 8,  16);
        const float ov = __shfl_sync(FULL, a, k + 12, 16);

        // c/h update — exact in r==0 lanes (a == i_k there); bounded junk elsewhere
        ch.c  = fmaf(fv, ch.c, a * gv);
        ch.hs = ov * tanh_fast(ch.c);

        // broadcast the 4 hidden values from the r==0 lanes (parallel)
        ch.h0 = __shfl_sync(FULL, ch.hs, 0, 16);
        ch.h1 = __shfl_sync(FULL, ch.hs, 1, 16);
        ch.h2 = __shfl_sync(FULL, ch.hs, 2, 16);
        ch.h3 = __shfl_sync(FULL, ch.hs, 3, 16);
    };

    // Staging: 512 float4 per chunk (32 elem x 16 quads); 256 threads x 2 each.
    const float4* xf4 = reinterpret_cast<const float4*>(x);
    const int f0 = t, f1 = t + 256;
    const int e0 = f0 >> 4, q0 = f0 & 15;
    const int e1 = f1 >> 4, q1 = f1 & 15;
    const size_t base0 = (size_t)(blockIdx.x * EPB + e0) * (T_STEPS * 2) + q0;
    const size_t base1 = (size_t)(blockIdx.x * EPB + e1) * (T_STEPS * 2) + q1;

    // Prologue: stage chunk 0.
    sm[0][e0 * STRIDE4 + q0] = xf4[base0];
    sm[0][e1 * STRIDE4 + q1] = xf4[base1];
    __syncthreads();

    for (int ck = 0; ck < NCHUNK; ck++) {
        float4 pf0, pf1;
        const bool more = (ck + 1 < NCHUNK);
        if (more) {
            pf0 = xf4[base0 + (size_t)(ck + 1) * 16];
            pf1 = xf4[base1 + (size_t)(ck + 1) * 16];
        }

        const float4* buf = sm[ck & 1];
        const ulonglong2* xA = reinterpret_cast<const ulonglong2*>(buf + eA * STRIDE4);
        const ulonglong2* xB = reinterpret_cast<const ulonglong2*>(buf + eB * STRIDE4);

#pragma unroll
        for (int sI = 0; sI < CH_STEPS; sI++) {
            const ulonglong2 aLo = xA[2 * sI], aHi = xA[2 * sI + 1];
            const ulonglong2 bLo = xB[2 * sI], bHi = xB[2 * sI + 1];
            STEP(cA, aLo, aHi);
            STEP(cB, bLo, bHi);
        }

        if (more) {
            float4* nbuf = sm[(ck + 1) & 1];
            nbuf[e0 * STRIDE4 + q0] = pf0;
            nbuf[e1 * STRIDE4 + q1] = pf1;
        }
        __syncthreads();
    }

    // ---- final FC ----
    if (u == 0) {
        out[bA] = fmaf(cA.h0, fcw[0], fmaf(cA.h1, fcw[1], fmaf(cA.h2, fcw[2], fmaf(cA.h3, fcw[3], fcb[0]))));
        out[bB] = fmaf(cB.h0, fcw[0], fmaf(cB.h1, fcw[1], fmaf(cB.h2, fcw[2], fmaf(cB.h3, fcw[3], fcb[0]))));
    }
}

extern "C" void kernel_launch(void* const* d_in, const int* in_sizes, int n_in,
                              void* d_out, int out_size)
{
    const float* x    = (const float*)d_in[0];
    const float* Wih  = (const float*)d_in[1];
    const float* Whh  = (const float*)d_in[2];
    const float* bih  = (const float*)d_in[3];
    const float* bhh  = (const float*)d_in[4];
    const float* fcw  = (const float*)d_in[5];
    const float* fcb  = (const float*)d_in[6];
    float* out = (float*)d_out;

    const int B = in_sizes[0] / (T_STEPS * I_DIM);   // 4096
    const int grid = B / EPB;                        // 128 blocks of 8 warps

    lstm_kernel<<<grid, BLOCK>>>(x, Wih, Whh, bih, bhh, fcw, fcb, out, B);
}

// round 12
// speedup vs baseline: 1.3826x; 1.3826x over previous
#include <cuda_runtime.h>

// LSTM_40948218200110: B=4096, T=1024, I=8, H=4 (PyTorch gate order) + FC[H->1].
// R10 = R7 shape (16 lanes/element, one chain/thread, 2048 warps) with:
//  - EPB=4 / BLOCK=64 / grid=1024 -> near-perfect SM load balance (28 vs 32 elem max)
//  - pair-interleaved smem so each LDS.128 serves both warp-groups in 1 wavefront
//  - XOR-butterfly exchange: 3 gate shfl (masks 4,8,12) + 8 SELs + 3 h shfl (1,2,3)
//    (6 shuffles/step instead of 7; c/h valid in all lanes)
// Packed fma.rn.f32x2 dot products; sigmoid 0.5-prescale folded into i/f/o weights.

#define T_STEPS 1024
#define I_DIM   8
#define EPB     4             // elements per block
#define BLOCK   64            // threads per block (2 warps, 2 pairs)
#define CH_STEPS 8            // timesteps per smem chunk
#define NCHUNK  (T_STEPS / CH_STEPS)   // 128

typedef unsigned long long ull;

__device__ __forceinline__ float tanh_fast(float x) {
    float y;
    asm("tanh.approx.f32 %0, %1;" : "=f"(y) : "f"(x));
    return y;
}
__device__ __forceinline__ ull ffma2(ull a, ull b, ull c) {
    ull d;
    asm("fma.rn.f32x2 %0, %1, %2, %3;" : "=l"(d) : "l"(a), "l"(b), "l"(c));
    return d;
}
__device__ __forceinline__ ull pack2(float lo, float hi) {
    ull d;
    asm("mov.b64 %0, {%1, %2};" : "=l"(d) : "f"(lo), "f"(hi));
    return d;
}
__device__ __forceinline__ float hsum2(ull v) {
    float lo, hi;
    asm("mov.b64 {%0, %1}, %2;" : "=f"(lo), "=f"(hi) : "l"(v));
    return lo + hi;
}

__global__ __launch_bounds__(BLOCK) void lstm_kernel(
    const float* __restrict__ x,     // [B, T, I]
    const float* __restrict__ Wih,   // [16, 8]
    const float* __restrict__ Whh,   // [16, 4]
    const float* __restrict__ bih,   // [16]
    const float* __restrict__ bhh,   // [16]
    const float* __restrict__ fcw,   // [1, 4]
    const float* __restrict__ fcb,   // [1]
    float* __restrict__ out,         // [B, 1]
    int B)
{
    // Per chunk: 2 pairs x 8 steps x 4 float4 (order per step: e0.lo, e1.lo, e0.hi, e1.hi)
    __shared__ float4 sm[2][EPB / 2 * CH_STEPS * 4];

    const int t = threadIdx.x;
    const int e = t >> 4;             // local element 0..3
    const int u = t & 15;             // lane within 16-group
    const int k = u & 3;              // hidden unit
    const int r = u >> 2;             // gate: 0=i,1=f,2=g,3=o
    const int pr = e >> 1;            // pair index (== warp id)
    const int half = e & 1;           // which element of the pair
    const int b = blockIdx.x * EPB + e;

    const int row = r * 4 + k;
    // sigmoid(z)=0.5*tanh(0.5z)+0.5 -> fold 0.5 into weights for i/f/o rows.
    const float s    = (r == 2) ? 1.0f : 0.5f;
    const float actM = (r == 2) ? 1.0f : 0.5f;
    const float actB = (r == 2) ? 0.0f : 0.5f;

    ull wx[4], wh[2], bia;
#pragma unroll
    for (int j = 0; j < 4; j++)
        wx[j] = pack2(s * Wih[row * I_DIM + 2 * j], s * Wih[row * I_DIM + 2 * j + 1]);
    // Recurrent weights permuted by k^m to pair with shfl_xor(h, m) results.
    wh[0] = pack2(s * Whh[row * 4 + (k ^ 0)], s * Whh[row * 4 + (k ^ 1)]);
    wh[1] = pack2(s * Whh[row * 4 + (k ^ 2)], s * Whh[row * 4 + (k ^ 3)]);
    bia = pack2(s * (bih[row] + bhh[row]), 0.0f);

    const bool s0 = (r & 1) != 0;     // gate-permute select bits
    const bool s1 = (r & 2) != 0;

    float hs = 0.f, hx1 = 0.f, hx2 = 0.f, hx3 = 0.f;   // h_k, h_{k^1}, h_{k^2}, h_{k^3}
    float c = 0.f;
    const unsigned FULL = 0xffffffffu;

    // Staging map: 64 float4 per chunk (4 elem x 16 quads), one per thread.
    // Thread f=t: elem e, quad q. Smem slot: pair*32 + step*4 + (q&1)*2 + half.
    const int qe = t >> 4, qq = t & 15;
    const int wslot = (qe >> 1) * (CH_STEPS * 4) + (qq >> 1) * 4 + (qq & 1) * 2 + (qe & 1);
    const float4* xf4 = reinterpret_cast<const float4*>(x);
    const size_t gbase = (size_t)(blockIdx.x * EPB + qe) * (T_STEPS * 2) + qq;

    // Compute-side base: this thread reads its pair's region, slots offset by `half`.
    const float4* mybase0 = &sm[0][pr * (CH_STEPS * 4) + half];
    const float4* mybase1 = &sm[1][pr * (CH_STEPS * 4) + half];

    // Prologue: stage chunk 0.
    sm[0][wslot] = xf4[gbase];
    __syncthreads();

    for (int ck = 0; ck < NCHUNK; ck++) {
        float4 pf;
        const bool more = (ck + 1 < NCHUNK);
        if (more) pf = xf4[gbase + (size_t)(ck + 1) * 16];

        const float4* mb = (ck & 1) ? mybase1 : mybase0;

#pragma unroll
        for (int sI = 0; sI < CH_STEPS; sI++) {
            // lo at slot sI*4 + half, hi at slot sI*4 + 2 + half (16B apart across pair)
            const ulonglong2 xlo = *reinterpret_cast<const ulonglong2*>(mb + sI * 4);
            const ulonglong2 xhi = *reinterpret_cast<const ulonglong2*>(mb + sI * 4 + 2);

            const ull h01 = pack2(hs,  hx1);
            const ull h23 = pack2(hx2, hx3);

            ull acc = ffma2(wx[0], xlo.x, bia);
            acc = ffma2(wx[1], xlo.y, acc);
            acc = ffma2(wx[2], xhi.x, acc);
            acc = ffma2(wx[3], xhi.y, acc);
            acc = ffma2(wh[0], h01, acc);            // recurrent (critical path)
            acc = ffma2(wh[1], h23, acc);
            const float z = hsum2(acc);

            const float a = fmaf(tanh_fast(z), actM, actB);   // own gate activation

            // butterfly gather: v_m = activation of gate (r^m), unit k
            const float v1 = __shfl_xor_sync(FULL, a, 4);
            const float v2 = __shfl_xor_sync(FULL, a, 8);
            const float v3 = __shfl_xor_sync(FULL, a, 12);

            // un-permute to (i,f,g,o): gate_j = v_{j^r}; two conditional-swap stages
            const float w0 = s0 ? v1 : a;
            const float w1 = s0 ? a  : v1;
            const float w2 = s0 ? v3 : v2;
            const float w3 = s0 ? v2 : v3;
            const float gi = s1 ? w2 : w0;
            const float gf = s1 ? w3 : w1;
            const float gg = s1 ? w0 : w2;
            const float go = s1 ? w1 : w3;

            // valid in ALL lanes: c_k, h_k
            c  = fmaf(gf, c, gi * gg);
            hs = go * tanh_fast(c);

            // h butterfly exchange (parallel, masks 1,2,3)
            hx1 = __shfl_xor_sync(FULL, hs, 1);
            hx2 = __shfl_xor_sync(FULL, hs, 2);
            hx3 = __shfl_xor_sync(FULL, hs, 3);
        }

        if (more) sm[(ck + 1) & 1][wslot] = pf;
        __syncthreads();
    }

    // ---- final FC: lane u==0 (r=0,k=0) has hs=h0, hx1=h1, hx2=h2, hx3=h3 ----
    if (u == 0) {
        out[b] = fmaf(hs, fcw[0], fmaf(hx1, fcw[1], fmaf(hx2, fcw[2], fmaf(hx3, fcw[3], fcb[0]))));
    }
}

extern "C" void kernel_launch(void* const* d_in, const int* in_sizes, int n_in,
                              void* d_out, int out_size)
{
    const float* x    = (const float*)d_in[0];
    const float* Wih  = (const float*)d_in[1];
    const float* Whh  = (const float*)d_in[2];
    const float* bih  = (const float*)d_in[3];
    const float* bhh  = (const float*)d_in[4];
    const float* fcw  = (const float*)d_in[5];
    const float* fcb  = (const float*)d_in[6];
    float* out = (float*)d_out;

    const int B = in_sizes[0] / (T_STEPS * I_DIM);   // 4096
    const int grid = B / EPB;                        // 1024 blocks of 2 warps

    lstm_kernel<<<grid, BLOCK>>>(x, Wih, Whh, bih, bhh, fcw, fcb, out, B);
}

// round 13
// speedup vs baseline: 1.4326x; 1.0361x over previous
#include <cuda_runtime.h>

// LSTM_40948218200110: B=4096, T=1024, I=8, H=4 (PyTorch gate order) + FC[H->1].
// R11 = R10 frame (16 lanes/elem, 2048 warps, EPB=4 balance, pair-interleaved
// LDS) with a SEL-free all-lanes-valid exchange:
//   - 4 computed-index width-16 gathers: iv,fv,gv,ov = shfl(a, k + 4m) — every
//     lane receives the true (i,f,g,o) activations of its unit; no un-permute.
//   - 3 parallel h butterflies (masks 1,2,3), recurrent weights k^m-permuted.
//   - recurrent dot product as two scalar FFMA chains (shorter critical path,
//     no pack movs); x-dot stays packed fma.rn.f32x2 (off the chain).

#define T_STEPS 1024
#define I_DIM   8
#define EPB     4             // elements per block
#define BLOCK   64            // threads per block (2 warps, 2 pairs)
#define CH_STEPS 8            // timesteps per smem chunk
#define NCHUNK  (T_STEPS / CH_STEPS)   // 128

typedef unsigned long long ull;

__device__ __forceinline__ float tanh_fast(float x) {
    float y;
    asm("tanh.approx.f32 %0, %1;" : "=f"(y) : "f"(x));
    return y;
}
__device__ __forceinline__ ull ffma2(ull a, ull b, ull c) {
    ull d;
    asm("fma.rn.f32x2 %0, %1, %2, %3;" : "=l"(d) : "l"(a), "l"(b), "l"(c));
    return d;
}
__device__ __forceinline__ ull pack2(float lo, float hi) {
    ull d;
    asm("mov.b64 %0, {%1, %2};" : "=l"(d) : "f"(lo), "f"(hi));
    return d;
}
__device__ __forceinline__ float hsum2(ull v) {
    float lo, hi;
    asm("mov.b64 {%0, %1}, %2;" : "=f"(lo), "=f"(hi) : "l"(v));
    return lo + hi;
}

__global__ __launch_bounds__(BLOCK) void lstm_kernel(
    const float* __restrict__ x,     // [B, T, I]
    const float* __restrict__ Wih,   // [16, 8]
    const float* __restrict__ Whh,   // [16, 4]
    const float* __restrict__ bih,   // [16]
    const float* __restrict__ bhh,   // [16]
    const float* __restrict__ fcw,   // [1, 4]
    const float* __restrict__ fcb,   // [1]
    float* __restrict__ out,         // [B, 1]
    int B)
{
    // Per chunk: 2 pairs x 8 steps x 4 float4 (order per step: e0.lo, e1.lo, e0.hi, e1.hi)
    __shared__ float4 sm[2][EPB / 2 * CH_STEPS * 4];

    const int t = threadIdx.x;
    const int e = t >> 4;             // local element 0..3
    const int u = t & 15;             // lane within 16-group
    const int k = u & 3;              // hidden unit
    const int r = u >> 2;             // gate: 0=i,1=f,2=g,3=o
    const int pr = e >> 1;            // pair index (== warp id)
    const int half = e & 1;           // which element of the pair
    const int b = blockIdx.x * EPB + e;

    const int row = r * 4 + k;
    // sigmoid(z)=0.5*tanh(0.5z)+0.5 -> fold 0.5 into weights for i/f/o rows.
    const float s    = (r == 2) ? 1.0f : 0.5f;
    const float actM = (r == 2) ? 1.0f : 0.5f;
    const float actB = (r == 2) ? 0.0f : 0.5f;

    // x weights packed (off-chain), recurrent weights scalar, k^m permuted so
    // uh[m] multiplies h_{k^m} (hx_m from the mask-m butterfly; hx_0 = own hs).
    ull wx[4], bia;
    float uh[4];
#pragma unroll
    for (int j = 0; j < 4; j++)
        wx[j] = pack2(s * Wih[row * I_DIM + 2 * j], s * Wih[row * I_DIM + 2 * j + 1]);
#pragma unroll
    for (int m = 0; m < 4; m++)
        uh[m] = s * Whh[row * 4 + (k ^ m)];
    bia = pack2(s * (bih[row] + bhh[row]), 0.0f);

    float hs = 0.f, hx1 = 0.f, hx2 = 0.f, hx3 = 0.f;   // h_k, h_{k^1}, h_{k^2}, h_{k^3}
    float c = 0.f;
    const unsigned FULL = 0xffffffffu;

    // Staging map: 64 float4 per chunk (4 elem x 16 quads), one per thread.
    const int qe = t >> 4, qq = t & 15;
    const int wslot = (qe >> 1) * (CH_STEPS * 4) + (qq >> 1) * 4 + (qq & 1) * 2 + (qe & 1);
    const float4* xf4 = reinterpret_cast<const float4*>(x);
    const size_t gbase = (size_t)(blockIdx.x * EPB + qe) * (T_STEPS * 2) + qq;

    const float4* mybase0 = &sm[0][pr * (CH_STEPS * 4) + half];
    const float4* mybase1 = &sm[1][pr * (CH_STEPS * 4) + half];

    // Prologue: stage chunk 0.
    sm[0][wslot] = xf4[gbase];
    __syncthreads();

    for (int ck = 0; ck < NCHUNK; ck++) {
        float4 pf;
        const bool more = (ck + 1 < NCHUNK);
        if (more) pf = xf4[gbase + (size_t)(ck + 1) * 16];

        const float4* mb = (ck & 1) ? mybase1 : mybase0;

#pragma unroll
        for (int sI = 0; sI < CH_STEPS; sI++) {
            const ulonglong2 xlo = *reinterpret_cast<const ulonglong2*>(mb + sI * 4);
            const ulonglong2 xhi = *reinterpret_cast<const ulonglong2*>(mb + sI * 4 + 2);

            // x-projection (packed, off the recurrent critical path)
            ull acc = ffma2(wx[0], xlo.x, bia);
            acc = ffma2(wx[1], xlo.y, acc);
            acc = ffma2(wx[2], xhi.x, acc);
            acc = ffma2(wx[3], xhi.y, acc);
            const float xz = hsum2(acc);

            // recurrent dot: two parallel scalar chains (short path from h arrival)
            const float z = fmaf(uh[0], hs, fmaf(uh[1], hx1, xz))
                          + fmaf(uh[2], hx2, uh[3] * hx3);

            const float a = fmaf(tanh_fast(z), actM, actB);   // own gate activation

            // all-lanes gather of the unit's four gate activations (width-16)
            const float iv = __shfl_sync(FULL, a, k,      16);
            const float fv = __shfl_sync(FULL, a, k + 4,  16);
            const float gv = __shfl_sync(FULL, a, k + 8,  16);
            const float ov = __shfl_sync(FULL, a, k + 12, 16);

            // valid in ALL lanes
            c  = fmaf(fv, c, iv * gv);
            hs = ov * tanh_fast(c);

            // h butterfly exchange (parallel, masks 1,2,3)
            hx1 = __shfl_xor_sync(FULL, hs, 1);
            hx2 = __shfl_xor_sync(FULL, hs, 2);
            hx3 = __shfl_xor_sync(FULL, hs, 3);
        }

        if (more) sm[(ck + 1) & 1][wslot] = pf;
        __syncthreads();
    }

    // ---- final FC: lane u==0 (r=0,k=0) has hs=h0, hx1=h1, hx2=h2, hx3=h3 ----
    if (u == 0) {
        out[b] = fmaf(hs, fcw[0], fmaf(hx1, fcw[1], fmaf(hx2, fcw[2], fmaf(hx3, fcw[3], fcb[0]))));
    }
}

extern "C" void kernel_launch(void* const* d_in, const int* in_sizes, int n_in,
                              void* d_out, int out_size)
{
    const float* x    = (const float*)d_in[0];
    const float* Wih  = (const float*)d_in[1];
    const float* Whh  = (const float*)d_in[2];
    const float* bih  = (const float*)d_in[3];
    const float* bhh  = (const float*)d_in[4];
    const float* fcw  = (const float*)d_in[5];
    const float* fcb  = (const float*)d_in[6];
    float* out = (float*)d_out;

    const int B = in_sizes[0] / (T_STEPS * I_DIM);   // 4096
    const int grid = B / EPB;                        // 1024 blocks of 2 warps

    lstm_kernel<<<grid, BLOCK>>>(x, Wih, Whh, bih, bhh, fcw, fcb, out, B);
}